// round 9
// baseline (speedup 1.0000x reference)
#include <cuda_runtime.h>
#include <cstddef>

// Sparsemax over last dim: rows of D=512 fp32, one warp per row.
// R9: decouple stores from tau. Sparsemax output is ~99% exact zeros
// (support ~3 of 512), so:
//   1) load row + immediately store a zero row (independent of tau -> the
//      store stream overlaps loads and the reduction; no pipeline bubble)
//   2) track per-lane top-2 (value,index) + a3 value during the load shadow
//   3) warm-started Michelot (tau0 = max-1) over the ~5 candidates
//   4) scatter-write the <=2 nonzero outputs per lane (same thread wrote the
//      zero at that address earlier => program order => overwrite wins)
// Rare overflow rows (some lane has >=3 candidates, ~3%, warp-uniform):
// full Michelot re-reading the row from L1, then full-row overwrite.

static constexpr int D   = 512;
static constexpr int VPT = 4;     // float4 per thread (4*4*32 = 512)
static constexpr int WPB = 8;     // warps (rows) per block

__device__ __forceinline__ float4 ld_ca_v4(const float4* p) {
    float4 r;
    asm volatile("ld.global.ca.v4.f32 {%0,%1,%2,%3}, [%4];"
                 : "=f"(r.x), "=f"(r.y), "=f"(r.z), "=f"(r.w)
                 : "l"(p));
    return r;
}

__global__ __launch_bounds__(WPB * 32, 8) void sparsemax_kernel(
    const float* __restrict__ x, float* __restrict__ y, int nrows)
{
    const int gwarp = (blockIdx.x * blockDim.x + threadIdx.x) >> 5;
    if (gwarp >= nrows) return;
    const int lane = threadIdx.x & 31;

    const float4* __restrict__ xr =
        reinterpret_cast<const float4*>(x) + (size_t)gwarp * (D / 4);
    float4* __restrict__ yr =
        reinterpret_cast<float4*>(y) + (size_t)gwarp * (D / 4);
    float* __restrict__ yrow = y + (size_t)gwarp * D;

    // ---- Front-batched loads, then independent zero-stores (no dependency
    // on tau: the store stream starts immediately). ----
    float4 v0 = __ldcs(&xr[lane +  0]);
    float4 v1 = __ldcs(&xr[lane + 32]);
    float4 v2 = __ldcs(&xr[lane + 64]);
    float4 v3 = __ldcs(&xr[lane + 96]);

    const float4 z4 = make_float4(0.f, 0.f, 0.f, 0.f);
    __stcs(&yr[lane +  0], z4);
    __stcs(&yr[lane + 32], z4);
    __stcs(&yr[lane + 64], z4);
    __stcs(&yr[lane + 96], z4);

    // ---- Per-lane top-2 (value,index) + a3 value, branchless selects. ----
    float a1 = -3.402823466e38f, a2 = a1, a3 = a1;
    int i1 = 0, i2 = 0;
    const float4 vv[VPT] = {v0, v1, v2, v3};
#pragma unroll
    for (int j = 0; j < VPT; j++) {
        const float e[4] = {vv[j].x, vv[j].y, vv[j].z, vv[j].w};
#pragma unroll
        for (int k = 0; k < 4; k++) {
            const int idx = (lane + 32 * j) * 4 + k;   // element index in row
            const float t = e[k];
            const bool g1 = t > a1;
            const bool g2 = t > a2;
            const bool g3 = t > a3;
            a3 = g2 ? a2 : (g3 ? t : a3);
            const float na2 = g1 ? a1 : (g2 ? t : a2);
            const int   ni2 = g1 ? i1 : (g2 ? idx : i2);
            a1 = g1 ? t : a1;
            i1 = g1 ? idx : i1;
            a2 = na2; i2 = ni2;
        }
    }

    float m = a1;
#pragma unroll
    for (int o = 16; o > 0; o >>= 1)
        m = fmaxf(m, __shfl_xor_sync(0xffffffffu, m, o));

    const float tau0 = m - 1.0f;   // tau* >= max - 1 (exact lower bound)
    float tau = tau0;

    if (__ballot_sync(0xffffffffu, a3 > tau0) == 0u) {
        // Fast path: all candidates {x > tau0} live in some lane's {a1,a2}.
        int prev = -1;
        for (;;) {
            float s = 0.0f;
            int c = 0;
            if (a1 > tau) { s += a1; c++; }
            if (a2 > tau) { s += a2; c++; }
#pragma unroll
            for (int o = 16; o > 0; o >>= 1)
                s += __shfl_xor_sync(0xffffffffu, s, o);
            c = __reduce_add_sync(0xffffffffu, c);
            if (c == prev) break;   // same count => same set => fixed point
            prev = c;
            tau = (s - 1.0f) / (float)c;
        }
        // Scatter the <=2 nonzero outputs per lane. Same thread wrote the
        // zero at these addresses above => program order => this wins.
        if (a1 > tau) yrow[i1] = a1 - tau;
        if (a2 > tau) yrow[i2] = a2 - tau;
    } else {
        // Rare overflow (warp-uniform): full Michelot from L1-resident row.
        int prev = -1;
        for (;;) {
            float s = 0.0f;
            int c = 0;
#pragma unroll
            for (int j = 0; j < VPT; j++) {
                const float4 t = ld_ca_v4(&xr[lane + 32 * j]);
                if (t.x > tau) { s += t.x; c++; }
                if (t.y > tau) { s += t.y; c++; }
                if (t.z > tau) { s += t.z; c++; }
                if (t.w > tau) { s += t.w; c++; }
            }
#pragma unroll
            for (int o = 16; o > 0; o >>= 1)
                s += __shfl_xor_sync(0xffffffffu, s, o);
            c = __reduce_add_sync(0xffffffffu, c);
            if (c == prev) break;
            prev = c;
            tau = (s - 1.0f) / (float)c;
        }
        // Full-row overwrite (same-thread ordering vs the zero stores).
#pragma unroll
        for (int j = 0; j < VPT; j++) {
            const float4 t = ld_ca_v4(&xr[lane + 32 * j]);
            float4 o;
            o.x = fmaxf(0.0f, t.x - tau);
            o.y = fmaxf(0.0f, t.y - tau);
            o.z = fmaxf(0.0f, t.z - tau);
            o.w = fmaxf(0.0f, t.w - tau);
            __stcs(&yr[lane + 32 * j], o);
        }
    }
}

extern "C" void kernel_launch(void* const* d_in, const int* in_sizes, int n_in,
                              void* d_out, int out_size)
{
    const float* x = (const float*)d_in[0];
    float* y = (float*)d_out;
    const int nrows = in_sizes[0] / D;              // 32*4096 = 131072
    const int blocks = (nrows + WPB - 1) / WPB;
    sparsemax_kernel<<<blocks, WPB * 32>>>(x, y, nrows);
}

// round 10
// speedup vs baseline: 1.0572x; 1.0572x over previous
#include <cuda_runtime.h>
#include <cstddef>

// Sparsemax over last dim: rows of D=512 fp32, one warp per row.
// R10 = R7 body + decoupled stores, WITHOUT index tracking.
//   1) 4 front-batched vector loads; immediately 4 vector ZERO stores
//      (independent of tau -> store stream overlaps loads + reduction).
//   2) R7's branchless per-lane top-3 VALUE network (no indices).
//   3) Warm-started Michelot: tau0 = max-1 is an exact lower bound
//      (max - tau* <= sum(max(x-tau*,0)) = 1); support shrinks monotonically;
//      count-stable termination => exact tau*.
//   4) Epilogue: 16 statically-indexed PREDICATED scalar stores
//      (@P STG, ~99% predicated off). Same thread wrote the zero at each
//      address first => program order => nonzero overwrite wins.
//   Fallback rows (some lane has >=3 candidates above tau0; warp-uniform,
//   ~3%): full register scan over resident v[], same epilogue.

static constexpr int D   = 512;
static constexpr int VPT = 4;     // float4 per thread (4*4*32 = 512)
static constexpr int WPB = 8;     // warps (rows) per block

__global__ __launch_bounds__(WPB * 32) void sparsemax_kernel(
    const float* __restrict__ x, float* __restrict__ y, int nrows)
{
    const int gwarp = (blockIdx.x * blockDim.x + threadIdx.x) >> 5;
    if (gwarp >= nrows) return;
    const int lane = threadIdx.x & 31;

    const float4* __restrict__ xr =
        reinterpret_cast<const float4*>(x) + (size_t)gwarp * (D / 4);
    float4* __restrict__ yr =
        reinterpret_cast<float4*>(y) + (size_t)gwarp * (D / 4);

    // ---- Front-batched loads; immediately start the (tau-independent)
    // zero-store stream. ----
    float4 v[VPT];
    v[0] = __ldcs(&xr[lane +  0]);
    v[1] = __ldcs(&xr[lane + 32]);
    v[2] = __ldcs(&xr[lane + 64]);
    v[3] = __ldcs(&xr[lane + 96]);

    const float4 z4 = make_float4(0.f, 0.f, 0.f, 0.f);
    __stcs(&yr[lane +  0], z4);
    __stcs(&yr[lane + 32], z4);
    __stcs(&yr[lane + 64], z4);
    __stcs(&yr[lane + 96], z4);

    // ---- R7's branchless per-lane top-3 (values only, no indices). ----
    float a1 = -3.402823466e38f, a2 = a1, a3 = a1;
#pragma unroll
    for (int j = 0; j < VPT; j++) {
        const float e[4] = {v[j].x, v[j].y, v[j].z, v[j].w};
#pragma unroll
        for (int k = 0; k < 4; k++) {
            const float n1 = fmaxf(a1, e[k]);
            const float r1 = fminf(a1, e[k]);
            const float n2 = fmaxf(a2, r1);
            const float r2 = fminf(a2, r1);
            a3 = fmaxf(a3, r2);
            a1 = n1; a2 = n2;
        }
    }
    float m = a1;
#pragma unroll
    for (int o = 16; o > 0; o >>= 1)
        m = fmaxf(m, __shfl_xor_sync(0xffffffffu, m, o));

    const float tau0 = m - 1.0f;   // exact lower bound on tau*
    float tau = tau0;

    if (__ballot_sync(0xffffffffu, a3 > tau0) == 0u) {
        // Fast path: every candidate {x > tau0} lies in some lane's {a1,a2}.
        int prev = -1;
        for (;;) {
            float s = 0.0f;
            int c = 0;
            if (a1 > tau) { s += a1; c++; }
            if (a2 > tau) { s += a2; c++; }
#pragma unroll
            for (int o = 16; o > 0; o >>= 1)
                s += __shfl_xor_sync(0xffffffffu, s, o);
            c = __reduce_add_sync(0xffffffffu, c);   // REDUX.SUM
            if (c == prev) break;   // same count => same set => fixed point
            prev = c;
            tau = (s - 1.0f) / (float)c;
        }
    } else {
        // Rare overflow (warp-uniform): full scan over resident v[].
        int prev = -1;
        for (;;) {
            float s = 0.0f;
            int c = 0;
#pragma unroll
            for (int j = 0; j < VPT; j++) {
                if (v[j].x > tau) { s += v[j].x; c++; }
                if (v[j].y > tau) { s += v[j].y; c++; }
                if (v[j].z > tau) { s += v[j].z; c++; }
                if (v[j].w > tau) { s += v[j].w; c++; }
            }
#pragma unroll
            for (int o = 16; o > 0; o >>= 1)
                s += __shfl_xor_sync(0xffffffffu, s, o);
            c = __reduce_add_sync(0xffffffffu, c);
            if (c == prev) break;
            prev = c;
            tau = (s - 1.0f) / (float)c;
        }
    }

    // ---- Epilogue: statically-indexed predicated sparse stores.
    // Element (j,k) lives at scalar offset k within yr[lane + 32*j];
    // ~99% of these predicate off (zero already written above by this
    // same thread, so program order makes the overwrite the final value).
#pragma unroll
    for (int j = 0; j < VPT; j++) {
        float* ys = reinterpret_cast<float*>(&yr[lane + 32 * j]);
        const float e[4] = {v[j].x, v[j].y, v[j].z, v[j].w};
#pragma unroll
        for (int k = 0; k < 4; k++) {
            if (e[k] > tau) ys[k] = e[k] - tau;
        }
    }
}

extern "C" void kernel_launch(void* const* d_in, const int* in_sizes, int n_in,
                              void* d_out, int out_size)
{
    const float* x = (const float*)d_in[0];
    float* y = (float*)d_out;
    const int nrows = in_sizes[0] / D;              // 32*4096 = 131072
    const int blocks = (nrows + WPB - 1) / WPB;
    sparsemax_kernel<<<blocks, WPB * 32>>>(x, y, nrows);
}